// round 16
// baseline (speedup 1.0000x reference)
#include <cuda_runtime.h>
#include <cuda_fp16.h>
#include <cstdint>
#include <math.h>

#define NB 64
#define NNODES 1296
#define NCLS 43
#define NCO 688                 // 43*16
#define PRI_STRIDE (NNODES*NCO) // 891648
#define CHUNK 8
#define NCHUNK 162              // 1296/8

// ---------------- scratch (static device arrays; no allocation) ----------------
__device__ __align__(16) __half g_w116[65536];       // conv1 w fp16 [k(243 pad 256)][oc 256]
__device__ __align__(16) __half g_a16[9437184];      // im2col A [36864][256] fp16
__device__ __align__(16) __half g_pw16[2097152];     // prim_w fp16 [k][oc=128]
__device__ __align__(16) __half g_h16[9437184];      // conv1 out fp16 NHWC [m=36864][256]
__device__ float  g_pp[8 * 5184 * 128];              // prim split-K partials
__device__ float  g_u[NB*NNODES*8];                  // squashed primary caps
__device__ __align__(16) __half g_priors16[57065472];// [b][n][c][o] fp16 (114 MB)
__device__ float  g_outv[NB*NCO];                    // outputs vector (b,c,o)
__device__ float  g_part[NB*NCHUNK*NCO];             // per-chunk partial s

// ---------------- mma / ldmatrix / cp.async primitives ----------------
__device__ __forceinline__ uint32_t smem_u32(const void* p) {
    uint32_t a;
    asm volatile("{ .reg .u64 t; cvta.to.shared.u64 t, %1; cvt.u32.u64 %0, t; }"
                 : "=r"(a) : "l"(p));
    return a;
}
__device__ __forceinline__ void ldm_x4(uint32_t& r0, uint32_t& r1, uint32_t& r2, uint32_t& r3, uint32_t addr) {
    asm volatile("ldmatrix.sync.aligned.m8n8.x4.shared.b16 {%0,%1,%2,%3},[%4];"
                 : "=r"(r0), "=r"(r1), "=r"(r2), "=r"(r3) : "r"(addr));
}
__device__ __forceinline__ void ldm_x4t(uint32_t& r0, uint32_t& r1, uint32_t& r2, uint32_t& r3, uint32_t addr) {
    asm volatile("ldmatrix.sync.aligned.m8n8.x4.trans.shared.b16 {%0,%1,%2,%3},[%4];"
                 : "=r"(r0), "=r"(r1), "=r"(r2), "=r"(r3) : "r"(addr));
}
__device__ __forceinline__ void mma16816(float* c, const uint32_t* a, const uint32_t* b) {
    asm volatile("mma.sync.aligned.m16n8k16.row.col.f32.f16.f16.f32 "
                 "{%0,%1,%2,%3},{%4,%5,%6,%7},{%8,%9},{%0,%1,%2,%3};"
                 : "+f"(c[0]), "+f"(c[1]), "+f"(c[2]), "+f"(c[3])
                 : "r"(a[0]), "r"(a[1]), "r"(a[2]), "r"(a[3]), "r"(b[0]), "r"(b[1]));
}
#define CPA(addr, ptr) asm volatile("cp.async.cg.shared.global [%0], [%1], 16;" :: "r"(addr), "l"(ptr))
#define CPA_COMMIT     asm volatile("cp.async.commit_group;")
#define CPA_WAIT0      asm volatile("cp.async.wait_group 0;")
#define CPA_WAIT1      asm volatile("cp.async.wait_group 1;")

// ------- fused weight transposes: blocks [0,128) = conv1 w, [128,640) = prim w --
__global__ void __launch_bounds__(256) k_tw(const float* __restrict__ w1,
                                            const float* __restrict__ wp) {
    __shared__ float s[32][129];
    int t = threadIdx.x;
    if (blockIdx.x < 128) {
        int i = blockIdx.x*256 + t;           // 32768 pairs
        int j = i * 2;                        // output index (k*256 + oc)
        int k = j >> 8, oc = j & 255;
        float v0 = 0.f, v1 = 0.f;
        if (k < 243) {
            int c = k / 81, r = k % 81, ky = r / 9, kx = r % 9;
            v0 = w1[(((oc  )*3 + c)*9 + ky)*9 + kx];
            v1 = w1[(((oc+1)*3 + c)*9 + ky)*9 + kx];
        }
        *(__half2*)&g_w116[j] = __floats2half2_rn(v0, v1);
    } else {
        int bid = blockIdx.x - 128;
        int bo = (bid & 3) * 32;              // oc tile
        int bk = (bid >> 2) * 128;            // kk tile
#pragma unroll
        for (int j = 0; j < 16; j++) {
            int idx = t + j*256;              // 4096 = 32 rows x 128 cols
            int r = idx >> 7, ccol = idx & 127;
            s[r][ccol] = wp[(bo + r)*16384 + bk + ccol];
        }
        __syncthreads();
#pragma unroll
        for (int j = 0; j < 8; j++) {         // 2048 half2 writes = 4096 elems
            int idx = t + j*256;
            int wr = idx >> 4, oc2 = (idx & 15) * 2;
            int kk = bk + wr;
            int ic = kk >> 6, pix = kk & 63;
            int k = (pix << 8) + ic;
            *(__half2*)&g_pw16[k*128 + bo + oc2] = __floats2half2_rn(s[oc2][wr], s[oc2+1][wr]);
        }
    }
}
__global__ void __launch_bounds__(256) k_im2col(const float* __restrict__ x) {
    int i = blockIdx.x*256 + threadIdx.x;     // 4718592 pairs
    int j = i * 2;
    int m = j >> 8, k = j & 255;
    int b = m / 576, r = m % 576, y = r / 24, x0 = r % 24;
    float v0 = 0.f, v1 = 0.f;
    if (k < 243) {
        int c = k / 81, rr = k % 81, ky = rr / 9, kx = rr % 9;
        v0 = x[((b*3 + c)*32 + (y + ky))*32 + (x0 + kx)];
    }
    if (k + 1 < 243) {
        int k1 = k + 1;
        int c = k1 / 81, rr = k1 % 81, ky = rr / 9, kx = rr % 9;
        v1 = x[((b*3 + c)*32 + (y + ky))*32 + (x0 + kx)];
    }
    *(__half2*)&g_a16[j] = __floats2half2_rn(v0, v1);
}

// ---------------- shared GEMM compute macro (64x128 tile, BK=64, 8 warps) ------
#define GEMM_COMPUTE(cbuf) { \
    const uint32_t sa_u = sa_base + (uint32_t)(cbuf) * 8192u; \
    const uint32_t sb_u = sb_base + (uint32_t)(cbuf) * 16384u; \
    _Pragma("unroll") \
    for (int ks = 0; ks < 4; ks++) { \
        uint32_t a[2][4]; \
        _Pragma("unroll") \
        for (int ai = 0; ai < 2; ai++) { \
            int r = wm*32 + ai*16 + (l & 15); \
            int c = ks*2 + (l >> 4); \
            uint32_t addr = sa_u + (uint32_t)(r*64 + ((c ^ (r & 7)) * 8)) * 2u; \
            ldm_x4(a[ai][0], a[ai][1], a[ai][2], a[ai][3], addr); \
        } \
        uint32_t bf[4][2]; \
        _Pragma("unroll") \
        for (int bp = 0; bp < 2; bp++) { \
            int r = ks*16 + (l & 15); \
            int c = wn*4 + bp*2 + (l >> 4); \
            uint32_t addr = sb_u + (uint32_t)(r*128 + ((c ^ (r & 7)) * 8)) * 2u; \
            uint32_t q0, q1, q2, q3; \
            ldm_x4t(q0, q1, q2, q3, addr); \
            bf[bp*2][0]   = q0; bf[bp*2][1]   = q1; \
            bf[bp*2+1][0] = q2; bf[bp*2+1][1] = q3; \
        } \
        _Pragma("unroll") \
        for (int ai = 0; ai < 2; ai++) \
            _Pragma("unroll") \
            for (int bi = 0; bi < 4; bi++) \
                mma16816(acc[ai][bi], a[ai], bf[bi]); \
    } \
}

// ------- conv1 as GEMM: M=36864, N=256 (2 halves), K=256 (243 padded) ---------
__global__ void __launch_bounds__(256) k_conv1_tc(const float* __restrict__ cb) {
    const int t = threadIdx.x;
    const int w = t >> 5, l = t & 31;
    const int m0 = blockIdx.x * 64;
    const int n0 = blockIdx.y * 128;

    __shared__ __align__(16) __half sA[2][64*64];
    __shared__ __align__(16) __half sB[2][64*128];

    const int ar = t >> 2;
    const int ac = (t & 3) * 2;
    const int am = m0 + ar;
    const int wm = w & 1, wn = w >> 1;

    float acc[2][4][4];
#pragma unroll
    for (int i = 0; i < 2; i++)
#pragma unroll
        for (int j = 0; j < 4; j++)
#pragma unroll
            for (int q = 0; q < 4; q++) acc[i][j][q] = 0.f;

    const uint32_t sa_base = smem_u32(&sA[0][0]);
    const uint32_t sb_base = smem_u32(&sB[0][0]);
#define CPLOAD1(it, buf) { \
    int k0 = (it)*64; \
    uint32_t da = sa_base + (uint32_t)(buf)*8192u; \
    const __half* pa = &g_a16[am*256 + k0 + ac*8]; \
    CPA(da + (uint32_t)(ar*64 + ((ac ^ (ar & 7)) * 8))*2u, pa); \
    CPA(da + (uint32_t)(ar*64 + (((ac+1) ^ (ar & 7)) * 8))*2u, pa + 8); \
    uint32_t db = sb_base + (uint32_t)(buf)*16384u; \
    _Pragma("unroll") \
    for (int j = 0; j < 4; j++) { \
        int id = t + j*256; \
        int rr = id >> 4, cc = id & 15; \
        CPA(db + (uint32_t)(rr*128 + ((cc ^ (rr & 7)) * 8))*2u, &g_w116[(k0 + rr)*256 + n0 + cc*8]); \
    } \
    CPA_COMMIT; \
}
    CPLOAD1(0, 0);
    CPA_WAIT0;
    __syncthreads();
    for (int it = 0; it < 4; it++) {
        if (it + 1 < 4) { CPLOAD1(it + 1, (it + 1) & 1); }
        GEMM_COMPUTE(it & 1)
        CPA_WAIT0;
        __syncthreads();
    }
#undef CPLOAD1

    // epilogue: +bias, relu, fp16 NHWC
#pragma unroll
    for (int ai = 0; ai < 2; ai++) {
#pragma unroll
        for (int bi = 0; bi < 4; bi++) {
            int mrow = m0 + wm*32 + ai*16 + (l >> 2);
            int ncol = n0 + wn*32 + bi*8 + (l & 3)*2;
            float b0 = cb[ncol], b1 = cb[ncol+1];
            *(__half2*)&g_h16[mrow*256 + ncol] =
                __floats2half2_rn(fmaxf(acc[ai][bi][0] + b0, 0.f), fmaxf(acc[ai][bi][1] + b1, 0.f));
            *(__half2*)&g_h16[(mrow+8)*256 + ncol] =
                __floats2half2_rn(fmaxf(acc[ai][bi][2] + b0, 0.f), fmaxf(acc[ai][bi][3] + b1, 0.f));
        }
    }
}

// ------- prim conv GEMM: M=5184, N=128, K=16384, split-K=8, 3-stage cp.async ---
__global__ void __launch_bounds__(256) k_prim_tc() {
    const int t = threadIdx.x;
    const int w = t >> 5, l = t & 31;
    const int m0 = blockIdx.x * 64;
    const int kbase = blockIdx.y * 2048;

    __shared__ __align__(16) __half sA[3][64*64];
    __shared__ __align__(16) __half sB[3][64*128];

    const int ar  = t >> 2;
    const int ac  = (t & 3) * 2;
    const int am  = m0 + ar;
    const int ab  = am / 81;
    const int arr = am % 81;
    const int aoy = arr / 9, aox = arr % 9;
    const int wm = w & 1, wn = w >> 1;

    float acc[2][4][4];
#pragma unroll
    for (int i = 0; i < 2; i++)
#pragma unroll
        for (int j = 0; j < 4; j++)
#pragma unroll
            for (int q = 0; q < 4; q++) acc[i][j][q] = 0.f;

    const uint32_t sa_base = smem_u32(&sA[0][0]);
    const uint32_t sb_base = smem_u32(&sB[0][0]);
#define CPLOADP(it, buf) { \
    int k0 = kbase + (it)*64; \
    int pix = k0 >> 8, ic0 = k0 & 255; \
    int ky = pix >> 3, kx = pix & 7; \
    const __half* pa = &g_h16[(((ab*24 + 2*aoy + ky)*24 + 2*aox + kx) << 8) + ic0 + ac*8]; \
    uint32_t da = sa_base + (uint32_t)(buf)*8192u; \
    CPA(da + (uint32_t)(ar*64 + ((ac ^ (ar & 7)) * 8))*2u, pa); \
    CPA(da + (uint32_t)(ar*64 + (((ac+1) ^ (ar & 7)) * 8))*2u, pa + 8); \
    uint32_t db = sb_base + (uint32_t)(buf)*16384u; \
    _Pragma("unroll") \
    for (int j = 0; j < 4; j++) { \
        int id = t + j*256; \
        int rr = id >> 4, cc = id & 15; \
        CPA(db + (uint32_t)(rr*128 + ((cc ^ (rr & 7)) * 8))*2u, &g_pw16[(k0 + rr)*128 + cc*8]); \
    } \
    CPA_COMMIT; \
}
    CPLOADP(0, 0);
    CPLOADP(1, 1);
    for (int it = 0; it < 32; it++) {
        if (it < 31) { CPA_WAIT1; } else { CPA_WAIT0; }
        __syncthreads();
        if (it + 2 < 32) { int nb3 = (it + 2) % 3; CPLOADP(it + 2, nb3); }
        GEMM_COMPUTE(it % 3)
    }
#undef CPLOADP

    const int skb = blockIdx.y * 5184;
#pragma unroll
    for (int ai = 0; ai < 2; ai++) {
#pragma unroll
        for (int bi = 0; bi < 4; bi++) {
            int mrow = m0 + wm*32 + ai*16 + (l >> 2);
            int ncol = wn*32 + bi*8 + (l & 3)*2;
            *(float2*)&g_pp[(skb + mrow)*128 + ncol]     = make_float2(acc[ai][bi][0], acc[ai][bi][1]);
            *(float2*)&g_pp[(skb + mrow + 8)*128 + ncol] = make_float2(acc[ai][bi][2], acc[ai][bi][3]);
        }
    }
}

// ------- reduce split-K + bias + squash -> g_u -------
__global__ void __launch_bounds__(256) k_psquash(const float* __restrict__ pbv) {
    int idx = blockIdx.x*256 + threadIdx.x;  // 82944
    int m = idx >> 4, d = idx & 15;
    float p[8]; float sn = 0.f;
#pragma unroll
    for (int i = 0; i < 8; i++) {
        float s = pbv[i*16 + d];
#pragma unroll
        for (int sk = 0; sk < 8; sk++) s += g_pp[(sk*5184 + m)*128 + i*16 + d];
        p[i] = s; sn += s*s;
    }
    float sc = sqrtf(sn) / (1.f + sn);
    int b = m / 81, rr = m % 81;
    float* up = &g_u[((b*NNODES) + d*81 + rr)*8];
    *(float4*)up       = make_float4(p[0]*sc, p[1]*sc, p[2]*sc, p[3]*sc);
    *(float4*)(up + 4) = make_float4(p[4]*sc, p[5]*sc, p[6]*sc, p[7]*sc);
}

// ------- priors[b,n,c,o] -> fp16 half2 coalesced; block per node, 352 thr ------
__global__ void __launch_bounds__(352) k_priors(const float* __restrict__ rw) {
    int n = blockIdx.x, t = threadIdx.x;
    __shared__ float su[512];
    __shared__ float sw[5504];
    for (int i = t; i < 5504; i += 352) sw[i] = rw[n*5504 + i];
    for (int i = t; i < 512;  i += 352) su[i] = g_u[((i>>3)*NNODES + n)*8 + (i&7)];
    __syncthreads();
    if (t < 344) {
        int j = t * 2;                   // j = c*16 + o (even o)
        int c = j >> 4, o = j & 15;
        float w0[8], w1[8];
#pragma unroll
        for (int i = 0; i < 8; i++) { w0[i] = sw[(c*8+i)*16 + o]; w1[i] = sw[(c*8+i)*16 + o + 1]; }
        for (int bb = 0; bb < 64; bb++) {
            float a0 = 0.f, a1 = 0.f;
#pragma unroll
            for (int i = 0; i < 8; i++) { float uu = su[bb*8+i]; a0 += uu*w0[i]; a1 += uu*w1[i]; }
            *(__half2*)&g_priors16[bb*PRI_STRIDE + n*NCO + j] = __floats2half2_rn(a0, a1);
        }
    }
}

// ------- pass A: streaming sum over n (no smem, no sync) -----------
__global__ void __launch_bounds__(344) k_sum0() {
    const int sp = blockIdx.x, b = blockIdx.y, t = threadIdx.x;
    const __half2* base = (const __half2*)&g_priors16[b*PRI_STRIDE + sp*108*NCO];
    float2 acc = make_float2(0.f, 0.f);
    for (int nn = 0; nn < 108; nn++) {
        float2 v = __half22float2(base[nn*344 + t]);
        acc.x += v.x; acc.y += v.y;
    }
    *(float2*)&g_part[(b*12 + sp)*NCO + t*2] = acc;
}

// ------- reduce 12 partials, *(1/43), squash -> g_outv (= out0) -------
__global__ void __launch_bounds__(704) k_s0squash() {
    int b = blockIdx.x, t = threadIdx.x;
    bool v = t < NCO;
    float s = 0.f;
    if (v) {
#pragma unroll
        for (int sp = 0; sp < 12; sp++) s += g_part[(b*12 + sp)*NCO + t];
        s *= (1.f/43.f);
    }
    float sn = s*s;
    sn += __shfl_xor_sync(0xffffffffu, sn, 8, 16);
    sn += __shfl_xor_sync(0xffffffffu, sn, 4, 16);
    sn += __shfl_xor_sync(0xffffffffu, sn, 2, 16);
    sn += __shfl_xor_sync(0xffffffffu, sn, 1, 16);
    if (v) g_outv[b*NCO + t] = s * (sqrtf(sn)/(1.f+sn));
}

// ------- routing pass: transposed smem layout [n][o*43+c] -> conflict-free ----
__global__ void __launch_bounds__(512) k_route() {
    const int ch = blockIdx.x, b = blockIdx.y, t = threadIdx.x;
    __shared__ float sp[CHUNK*NCO];   // [n][o*43 + c]
    __shared__ float sov[NCO];        // [o*43 + c]
    __shared__ float sd[CHUNK*NCLS];  // 344
    __shared__ float sinv[CHUNK];

    // stage priors chunk, transposing (c,o) -> (o,c) per node
    {
        const __half2* src = (const __half2*)&g_priors16[b*PRI_STRIDE + ch*CHUNK*NCO];
        for (int i = t; i < CHUNK*NCO/2; i += 512) {
            float2 v = __half22float2(src[i]);
            int j = i*2;
            int n = j / NCO, rem = j - n*NCO;
            int c = rem >> 4, o = rem & 15;
            sp[n*NCO + o*43 + c]     = v.x;
            sp[n*NCO + (o+1)*43 + c] = v.y;
        }
    }
    for (int i = t; i < NCO; i += 512) {
        int o = i / 43, c = i - o*43;
        sov[i] = g_outv[b*NCO + c*16 + o];
    }
    __syncthreads();

    // delta: t<344 -> (n, c); stride-1 smem accesses across lanes
    if (t < CHUNK*NCLS) {
        int n = t / NCLS, c = t - (t / NCLS)*NCLS;
        float d = 0.f;
#pragma unroll
        for (int o = 0; o < 16; o++)
            d += sp[n*NCO + o*43 + c] * sov[o*43 + c];
        sd[t] = __expf(d);    // logits are O(1); max-subtraction unnecessary
    }
    __syncthreads();
    if (t < CHUNK) {
        float s = 0.f;
        for (int c = 0; c < NCLS; c++) s += sd[t*NCLS + c];
        sinv[t] = 1.f / s;
    }
    __syncthreads();

    // weighted sum; output stays in (c*16+o) order for g_part
    for (int i = t; i < NCO; i += 512) {
        int c = i >> 4, o = i & 15;
        int ti = o*43 + c;
        float acc = 0.f;
#pragma unroll
        for (int n = 0; n < CHUNK; n++)
            acc += (sd[n*NCLS + c] * sinv[n]) * sp[n*NCO + ti];
        g_part[(b*NCHUNK + ch)*NCO + i] = acc;
    }
}

// ------- reduce partials -> squash; g_outv += (accumulates out0+out1) -------
__global__ void __launch_bounds__(704) k_rsquash() {
    int b = blockIdx.x, t = threadIdx.x;
    bool v = t < NCO;
    float s = 0.f;
    if (v) for (int ch = 0; ch < NCHUNK; ch++) s += g_part[(b*NCHUNK+ch)*NCO + t];
    float sn = s*s;
    sn += __shfl_xor_sync(0xffffffffu, sn, 8, 16);
    sn += __shfl_xor_sync(0xffffffffu, sn, 4, 16);
    sn += __shfl_xor_sync(0xffffffffu, sn, 2, 16);
    sn += __shfl_xor_sync(0xffffffffu, sn, 1, 16);
    if (v) g_outv[b*NCO + t] += s * (sqrtf(sn)/(1.f+sn));
}

// ------- final: scores = sn/(1+sn) -------
__global__ void __launch_bounds__(704) k_rfinal(float* __restrict__ out) {
    int b = blockIdx.x, t = threadIdx.x;
    bool v = t < NCO;
    float s = 0.f;
    if (v) for (int ch = 0; ch < NCHUNK; ch++) s += g_part[(b*NCHUNK+ch)*NCO + t];
    float sn = s*s;
    sn += __shfl_xor_sync(0xffffffffu, sn, 8, 16);
    sn += __shfl_xor_sync(0xffffffffu, sn, 4, 16);
    sn += __shfl_xor_sync(0xffffffffu, sn, 2, 16);
    sn += __shfl_xor_sync(0xffffffffu, sn, 1, 16);
    if (v && (t & 15) == 0) out[b*NCLS + (t >> 4)] = sn / (1.f + sn);
}

extern "C" void kernel_launch(void* const* d_in, const int* in_sizes, int n_in,
                              void* d_out, int out_size) {
    const float* x  = (const float*)d_in[0];
    const float* cw = (const float*)d_in[1];
    const float* cb = (const float*)d_in[2];
    const float* pw = (const float*)d_in[3];
    const float* pb = (const float*)d_in[4];
    const float* rw = (const float*)d_in[5];
    float* out = (float*)d_out;

    k_tw<<<640, 256>>>(cw, pw);
    k_im2col<<<18432, 256>>>(x);
    k_conv1_tc<<<dim3(576, 2), 256>>>(cb);
    k_prim_tc<<<dim3(81, 8), 256>>>();      // 4th launch -> ncu capture target
    k_psquash<<<324, 256>>>(pb);
    k_priors<<<1296, 352>>>(rw);
    k_sum0<<<dim3(12, 64), 344>>>();
    k_s0squash<<<64, 704>>>();
    k_route<<<dim3(NCHUNK, 64), 512>>>();
    k_rsquash<<<64, 704>>>();
    k_route<<<dim3(NCHUNK, 64), 512>>>();
    k_rfinal<<<64, 704>>>(out);
}

// round 17
// speedup vs baseline: 1.4254x; 1.4254x over previous
#include <cuda_runtime.h>
#include <cuda_fp16.h>
#include <cstdint>
#include <math.h>

#define NB 64
#define NNODES 1296
#define NCLS 43
#define NCO 688                 // 43*16
#define PRI_STRIDE (NNODES*NCO) // 891648
#define CHUNK 8
#define NCHUNK 162              // 1296/8

// ---------------- scratch (static device arrays; no allocation) ----------------
__device__ __align__(16) __half g_w116[65536];       // conv1 w fp16 [k(243 pad 256)][oc 256]
__device__ __align__(16) __half g_a16[9437184];      // im2col A [36864][256] fp16
__device__ __align__(16) __half g_pw16[2097152];     // prim_w fp16 [k][oc=128]
__device__ __align__(16) __half g_h16[9437184];      // conv1 out fp16 NHWC [m=36864][256]
__device__ float  g_pp[8 * 5184 * 128];              // prim split-K partials
__device__ float  g_u[NB*NNODES*8];                  // squashed primary caps
__device__ __align__(16) __half g_priors16[57065472];// [b][n][c][o] fp16 (114 MB)
__device__ float  g_outv[NB*NCO];                    // outputs vector (b,c,o)
__device__ float  g_part[NB*NCHUNK*NCO];             // per-chunk partial s

// ---------------- mma / ldmatrix / cp.async primitives ----------------
__device__ __forceinline__ uint32_t smem_u32(const void* p) {
    uint32_t a;
    asm volatile("{ .reg .u64 t; cvta.to.shared.u64 t, %1; cvt.u32.u64 %0, t; }"
                 : "=r"(a) : "l"(p));
    return a;
}
__device__ __forceinline__ void ldm_x4(uint32_t& r0, uint32_t& r1, uint32_t& r2, uint32_t& r3, uint32_t addr) {
    asm volatile("ldmatrix.sync.aligned.m8n8.x4.shared.b16 {%0,%1,%2,%3},[%4];"
                 : "=r"(r0), "=r"(r1), "=r"(r2), "=r"(r3) : "r"(addr));
}
__device__ __forceinline__ void ldm_x4t(uint32_t& r0, uint32_t& r1, uint32_t& r2, uint32_t& r3, uint32_t addr) {
    asm volatile("ldmatrix.sync.aligned.m8n8.x4.trans.shared.b16 {%0,%1,%2,%3},[%4];"
                 : "=r"(r0), "=r"(r1), "=r"(r2), "=r"(r3) : "r"(addr));
}
__device__ __forceinline__ void mma16816(float* c, const uint32_t* a, const uint32_t* b) {
    asm volatile("mma.sync.aligned.m16n8k16.row.col.f32.f16.f16.f32 "
                 "{%0,%1,%2,%3},{%4,%5,%6,%7},{%8,%9},{%0,%1,%2,%3};"
                 : "+f"(c[0]), "+f"(c[1]), "+f"(c[2]), "+f"(c[3])
                 : "r"(a[0]), "r"(a[1]), "r"(a[2]), "r"(a[3]), "r"(b[0]), "r"(b[1]));
}
#define CPA(addr, ptr) asm volatile("cp.async.cg.shared.global [%0], [%1], 16;" :: "r"(addr), "l"(ptr))
#define CPA_COMMIT     asm volatile("cp.async.commit_group;")
#define CPA_WAIT0      asm volatile("cp.async.wait_group 0;")
#define CPA_WAIT1      asm volatile("cp.async.wait_group 1;")

// ------- fused weight transposes: blocks [0,128) = conv1 w, [128,640) = prim w --
__global__ void __launch_bounds__(256) k_tw(const float* __restrict__ w1,
                                            const float* __restrict__ wp) {
    __shared__ float s[32][129];
    int t = threadIdx.x;
    if (blockIdx.x < 128) {
        int i = blockIdx.x*256 + t;           // 32768 pairs
        int j = i * 2;                        // output index (k*256 + oc)
        int k = j >> 8, oc = j & 255;
        float v0 = 0.f, v1 = 0.f;
        if (k < 243) {
            int c = k / 81, r = k % 81, ky = r / 9, kx = r % 9;
            v0 = w1[(((oc  )*3 + c)*9 + ky)*9 + kx];
            v1 = w1[(((oc+1)*3 + c)*9 + ky)*9 + kx];
        }
        *(__half2*)&g_w116[j] = __floats2half2_rn(v0, v1);
    } else {
        int bid = blockIdx.x - 128;
        int bo = (bid & 3) * 32;              // oc tile
        int bk = (bid >> 2) * 128;            // kk tile
#pragma unroll
        for (int j = 0; j < 16; j++) {
            int idx = t + j*256;              // 4096 = 32 rows x 128 cols
            int r = idx >> 7, ccol = idx & 127;
            s[r][ccol] = wp[(bo + r)*16384 + bk + ccol];
        }
        __syncthreads();
#pragma unroll
        for (int j = 0; j < 8; j++) {         // 2048 half2 writes = 4096 elems
            int idx = t + j*256;
            int wr = idx >> 4, oc2 = (idx & 15) * 2;
            int kk = bk + wr;
            int ic = kk >> 6, pix = kk & 63;
            int k = (pix << 8) + ic;
            *(__half2*)&g_pw16[k*128 + bo + oc2] = __floats2half2_rn(s[oc2][wr], s[oc2+1][wr]);
        }
    }
}
__global__ void __launch_bounds__(256) k_im2col(const float* __restrict__ x) {
    int i = blockIdx.x*256 + threadIdx.x;     // 4718592 pairs
    int j = i * 2;
    int m = j >> 8, k = j & 255;
    int b = m / 576, r = m % 576, y = r / 24, x0 = r % 24;
    float v0 = 0.f, v1 = 0.f;
    if (k < 243) {
        int c = k / 81, rr = k % 81, ky = rr / 9, kx = rr % 9;
        v0 = x[((b*3 + c)*32 + (y + ky))*32 + (x0 + kx)];
    }
    if (k + 1 < 243) {
        int k1 = k + 1;
        int c = k1 / 81, rr = k1 % 81, ky = rr / 9, kx = rr % 9;
        v1 = x[((b*3 + c)*32 + (y + ky))*32 + (x0 + kx)];
    }
    *(__half2*)&g_a16[j] = __floats2half2_rn(v0, v1);
}

// ---------------- shared GEMM compute macro (64x128 tile, BK=64, 8 warps) ------
#define GEMM_COMPUTE(cbuf) { \
    const uint32_t sa_u = sa_base + (uint32_t)(cbuf) * 8192u; \
    const uint32_t sb_u = sb_base + (uint32_t)(cbuf) * 16384u; \
    _Pragma("unroll") \
    for (int ks = 0; ks < 4; ks++) { \
        uint32_t a[2][4]; \
        _Pragma("unroll") \
        for (int ai = 0; ai < 2; ai++) { \
            int r = wm*32 + ai*16 + (l & 15); \
            int c = ks*2 + (l >> 4); \
            uint32_t addr = sa_u + (uint32_t)(r*64 + ((c ^ (r & 7)) * 8)) * 2u; \
            ldm_x4(a[ai][0], a[ai][1], a[ai][2], a[ai][3], addr); \
        } \
        uint32_t bf[4][2]; \
        _Pragma("unroll") \
        for (int bp = 0; bp < 2; bp++) { \
            int r = ks*16 + (l & 15); \
            int c = wn*4 + bp*2 + (l >> 4); \
            uint32_t addr = sb_u + (uint32_t)(r*128 + ((c ^ (r & 7)) * 8)) * 2u; \
            uint32_t q0, q1, q2, q3; \
            ldm_x4t(q0, q1, q2, q3, addr); \
            bf[bp*2][0]   = q0; bf[bp*2][1]   = q1; \
            bf[bp*2+1][0] = q2; bf[bp*2+1][1] = q3; \
        } \
        _Pragma("unroll") \
        for (int ai = 0; ai < 2; ai++) \
            _Pragma("unroll") \
            for (int bi = 0; bi < 4; bi++) \
                mma16816(acc[ai][bi], a[ai], bf[bi]); \
    } \
}

// ------- conv1 as GEMM: M=36864, N=256 (2 halves), K=256 (243 padded) ---------
__global__ void __launch_bounds__(256) k_conv1_tc(const float* __restrict__ cb) {
    const int t = threadIdx.x;
    const int w = t >> 5, l = t & 31;
    const int m0 = blockIdx.x * 64;
    const int n0 = blockIdx.y * 128;

    __shared__ __align__(16) __half sA[2][64*64];
    __shared__ __align__(16) __half sB[2][64*128];

    const int ar = t >> 2;
    const int ac = (t & 3) * 2;
    const int am = m0 + ar;
    const int wm = w & 1, wn = w >> 1;

    float acc[2][4][4];
#pragma unroll
    for (int i = 0; i < 2; i++)
#pragma unroll
        for (int j = 0; j < 4; j++)
#pragma unroll
            for (int q = 0; q < 4; q++) acc[i][j][q] = 0.f;

    const uint32_t sa_base = smem_u32(&sA[0][0]);
    const uint32_t sb_base = smem_u32(&sB[0][0]);
#define CPLOAD1(it, buf) { \
    int k0 = (it)*64; \
    uint32_t da = sa_base + (uint32_t)(buf)*8192u; \
    const __half* pa = &g_a16[am*256 + k0 + ac*8]; \
    CPA(da + (uint32_t)(ar*64 + ((ac ^ (ar & 7)) * 8))*2u, pa); \
    CPA(da + (uint32_t)(ar*64 + (((ac+1) ^ (ar & 7)) * 8))*2u, pa + 8); \
    uint32_t db = sb_base + (uint32_t)(buf)*16384u; \
    _Pragma("unroll") \
    for (int j = 0; j < 4; j++) { \
        int id = t + j*256; \
        int rr = id >> 4, cc = id & 15; \
        CPA(db + (uint32_t)(rr*128 + ((cc ^ (rr & 7)) * 8))*2u, &g_w116[(k0 + rr)*256 + n0 + cc*8]); \
    } \
    CPA_COMMIT; \
}
    CPLOAD1(0, 0);
    CPA_WAIT0;
    __syncthreads();
    for (int it = 0; it < 4; it++) {
        if (it + 1 < 4) { CPLOAD1(it + 1, (it + 1) & 1); }
        GEMM_COMPUTE(it & 1)
        CPA_WAIT0;
        __syncthreads();
    }
#undef CPLOAD1

    // epilogue: +bias, relu, fp16 NHWC
#pragma unroll
    for (int ai = 0; ai < 2; ai++) {
#pragma unroll
        for (int bi = 0; bi < 4; bi++) {
            int mrow = m0 + wm*32 + ai*16 + (l >> 2);
            int ncol = n0 + wn*32 + bi*8 + (l & 3)*2;
            float b0 = cb[ncol], b1 = cb[ncol+1];
            *(__half2*)&g_h16[mrow*256 + ncol] =
                __floats2half2_rn(fmaxf(acc[ai][bi][0] + b0, 0.f), fmaxf(acc[ai][bi][1] + b1, 0.f));
            *(__half2*)&g_h16[(mrow+8)*256 + ncol] =
                __floats2half2_rn(fmaxf(acc[ai][bi][2] + b0, 0.f), fmaxf(acc[ai][bi][3] + b1, 0.f));
        }
    }
}

// ------- prim conv GEMM: M=5184, N=128, K=16384, split-K=8, 3-stage cp.async ---
__global__ void __launch_bounds__(256) k_prim_tc() {
    const int t = threadIdx.x;
    const int w = t >> 5, l = t & 31;
    const int m0 = blockIdx.x * 64;
    const int kbase = blockIdx.y * 2048;

    __shared__ __align__(16) __half sA[3][64*64];
    __shared__ __align__(16) __half sB[3][64*128];

    const int ar  = t >> 2;
    const int ac  = (t & 3) * 2;
    const int am  = m0 + ar;
    const int ab  = am / 81;
    const int arr = am % 81;
    const int aoy = arr / 9, aox = arr % 9;
    const int wm = w & 1, wn = w >> 1;

    float acc[2][4][4];
#pragma unroll
    for (int i = 0; i < 2; i++)
#pragma unroll
        for (int j = 0; j < 4; j++)
#pragma unroll
            for (int q = 0; q < 4; q++) acc[i][j][q] = 0.f;

    const uint32_t sa_base = smem_u32(&sA[0][0]);
    const uint32_t sb_base = smem_u32(&sB[0][0]);
#define CPLOADP(it, buf) { \
    int k0 = kbase + (it)*64; \
    int pix = k0 >> 8, ic0 = k0 & 255; \
    int ky = pix >> 3, kx = pix & 7; \
    const __half* pa = &g_h16[(((ab*24 + 2*aoy + ky)*24 + 2*aox + kx) << 8) + ic0 + ac*8]; \
    uint32_t da = sa_base + (uint32_t)(buf)*8192u; \
    CPA(da + (uint32_t)(ar*64 + ((ac ^ (ar & 7)) * 8))*2u, pa); \
    CPA(da + (uint32_t)(ar*64 + (((ac+1) ^ (ar & 7)) * 8))*2u, pa + 8); \
    uint32_t db = sb_base + (uint32_t)(buf)*16384u; \
    _Pragma("unroll") \
    for (int j = 0; j < 4; j++) { \
        int id = t + j*256; \
        int rr = id >> 4, cc = id & 15; \
        CPA(db + (uint32_t)(rr*128 + ((cc ^ (rr & 7)) * 8))*2u, &g_pw16[(k0 + rr)*128 + cc*8]); \
    } \
    CPA_COMMIT; \
}
    CPLOADP(0, 0);
    CPLOADP(1, 1);
    for (int it = 0; it < 32; it++) {
        if (it < 31) { CPA_WAIT1; } else { CPA_WAIT0; }
        __syncthreads();
        if (it + 2 < 32) { int nb3 = (it + 2) % 3; CPLOADP(it + 2, nb3); }
        GEMM_COMPUTE(it % 3)
    }
#undef CPLOADP

    const int skb = blockIdx.y * 5184;
#pragma unroll
    for (int ai = 0; ai < 2; ai++) {
#pragma unroll
        for (int bi = 0; bi < 4; bi++) {
            int mrow = m0 + wm*32 + ai*16 + (l >> 2);
            int ncol = wn*32 + bi*8 + (l & 3)*2;
            *(float2*)&g_pp[(skb + mrow)*128 + ncol]     = make_float2(acc[ai][bi][0], acc[ai][bi][1]);
            *(float2*)&g_pp[(skb + mrow + 8)*128 + ncol] = make_float2(acc[ai][bi][2], acc[ai][bi][3]);
        }
    }
}

// ------- reduce split-K + bias + squash -> g_u -------
__global__ void __launch_bounds__(256) k_psquash(const float* __restrict__ pbv) {
    int idx = blockIdx.x*256 + threadIdx.x;  // 82944
    int m = idx >> 4, d = idx & 15;
    float p[8]; float sn = 0.f;
#pragma unroll
    for (int i = 0; i < 8; i++) {
        float s = pbv[i*16 + d];
#pragma unroll
        for (int sk = 0; sk < 8; sk++) s += g_pp[(sk*5184 + m)*128 + i*16 + d];
        p[i] = s; sn += s*s;
    }
    float sc = sqrtf(sn) / (1.f + sn);
    int b = m / 81, rr = m % 81;
    float* up = &g_u[((b*NNODES) + d*81 + rr)*8];
    *(float4*)up       = make_float4(p[0]*sc, p[1]*sc, p[2]*sc, p[3]*sc);
    *(float4*)(up + 4) = make_float4(p[4]*sc, p[5]*sc, p[6]*sc, p[7]*sc);
}

// ------- priors[b,n,c,o] -> fp16 half2 coalesced; block per node, 352 thr ------
__global__ void __launch_bounds__(352) k_priors(const float* __restrict__ rw) {
    int n = blockIdx.x, t = threadIdx.x;
    __shared__ float su[512];
    __shared__ float sw[5504];
    for (int i = t; i < 5504; i += 352) sw[i] = rw[n*5504 + i];
    for (int i = t; i < 512;  i += 352) su[i] = g_u[((i>>3)*NNODES + n)*8 + (i&7)];
    __syncthreads();
    if (t < 344) {
        int j = t * 2;                   // j = c*16 + o (even o)
        int c = j >> 4, o = j & 15;
        float w0[8], w1[8];
#pragma unroll
        for (int i = 0; i < 8; i++) { w0[i] = sw[(c*8+i)*16 + o]; w1[i] = sw[(c*8+i)*16 + o + 1]; }
        for (int bb = 0; bb < 64; bb++) {
            float a0 = 0.f, a1 = 0.f;
#pragma unroll
            for (int i = 0; i < 8; i++) { float uu = su[bb*8+i]; a0 += uu*w0[i]; a1 += uu*w1[i]; }
            *(__half2*)&g_priors16[bb*PRI_STRIDE + n*NCO + j] = __floats2half2_rn(a0, a1);
        }
    }
}

// ------- pass A: streaming sum over n (no smem, no sync) -----------
__global__ void __launch_bounds__(344) k_sum0() {
    const int sp = blockIdx.x, b = blockIdx.y, t = threadIdx.x;
    const __half2* base = (const __half2*)&g_priors16[b*PRI_STRIDE + sp*108*NCO];
    float2 acc = make_float2(0.f, 0.f);
    for (int nn = 0; nn < 108; nn++) {
        float2 v = __half22float2(base[nn*344 + t]);
        acc.x += v.x; acc.y += v.y;
    }
    *(float2*)&g_part[(b*12 + sp)*NCO + t*2] = acc;
}

// ------- reduce 12 partials, *(1/43), squash -> g_outv (= out0) -------
__global__ void __launch_bounds__(704) k_s0squash() {
    int b = blockIdx.x, t = threadIdx.x;
    bool v = t < NCO;
    float s = 0.f;
    if (v) {
#pragma unroll
        for (int sp = 0; sp < 12; sp++) s += g_part[(b*12 + sp)*NCO + t];
        s *= (1.f/43.f);
    }
    float sn = s*s;
    sn += __shfl_xor_sync(0xffffffffu, sn, 8, 16);
    sn += __shfl_xor_sync(0xffffffffu, sn, 4, 16);
    sn += __shfl_xor_sync(0xffffffffu, sn, 2, 16);
    sn += __shfl_xor_sync(0xffffffffu, sn, 1, 16);
    if (v) g_outv[b*NCO + t] = s * (sqrtf(sn)/(1.f+sn));
}

// ------- routing pass: transposed smem layout [n][o*43+c] -> conflict-free ----
__global__ void __launch_bounds__(512) k_route() {
    const int ch = blockIdx.x, b = blockIdx.y, t = threadIdx.x;
    __shared__ float sp[CHUNK*NCO];   // [n][o*43 + c]
    __shared__ float sov[NCO];        // [o*43 + c]
    __shared__ float sd[CHUNK*NCLS];  // 344
    __shared__ float sinv[CHUNK];

    // stage priors chunk, transposing (c,o) -> (o,c) per node
    {
        const __half2* src = (const __half2*)&g_priors16[b*PRI_STRIDE + ch*CHUNK*NCO];
        for (int i = t; i < CHUNK*NCO/2; i += 512) {
            float2 v = __half22float2(src[i]);
            int j = i*2;
            int n = j / NCO, rem = j - n*NCO;
            int c = rem >> 4, o = rem & 15;
            sp[n*NCO + o*43 + c]     = v.x;
            sp[n*NCO + (o+1)*43 + c] = v.y;
        }
    }
    for (int i = t; i < NCO; i += 512) {
        int o = i / 43, c = i - o*43;
        sov[i] = g_outv[b*NCO + c*16 + o];
    }
    __syncthreads();

    // delta: t<344 -> (n, c); stride-1 smem accesses across lanes
    if (t < CHUNK*NCLS) {
        int n = t / NCLS, c = t - (t / NCLS)*NCLS;
        float d = 0.f;
#pragma unroll
        for (int o = 0; o < 16; o++)
            d += sp[n*NCO + o*43 + c] * sov[o*43 + c];
        sd[t] = __expf(d);    // logits are O(1); max-subtraction unnecessary
    }
    __syncthreads();
    if (t < CHUNK) {
        float s = 0.f;
        for (int c = 0; c < NCLS; c++) s += sd[t*NCLS + c];
        sinv[t] = 1.f / s;
    }
    __syncthreads();

    // weighted sum; output stays in (c*16+o) order for g_part
    for (int i = t; i < NCO; i += 512) {
        int c = i >> 4, o = i & 15;
        int ti = o*43 + c;
        float acc = 0.f;
#pragma unroll
        for (int n = 0; n < CHUNK; n++)
            acc += (sd[n*NCLS + c] * sinv[n]) * sp[n*NCO + ti];
        g_part[(b*NCHUNK + ch)*NCO + i] = acc;
    }
}

// ------- reduce partials -> squash; g_outv += (accumulates out0+out1) -------
__global__ void __launch_bounds__(704) k_rsquash() {
    int b = blockIdx.x, t = threadIdx.x;
    bool v = t < NCO;
    float s = 0.f;
    if (v) for (int ch = 0; ch < NCHUNK; ch++) s += g_part[(b*NCHUNK+ch)*NCO + t];
    float sn = s*s;
    sn += __shfl_xor_sync(0xffffffffu, sn, 8, 16);
    sn += __shfl_xor_sync(0xffffffffu, sn, 4, 16);
    sn += __shfl_xor_sync(0xffffffffu, sn, 2, 16);
    sn += __shfl_xor_sync(0xffffffffu, sn, 1, 16);
    if (v) g_outv[b*NCO + t] += s * (sqrtf(sn)/(1.f+sn));
}

// ------- final: scores = sn/(1+sn) -------
__global__ void __launch_bounds__(704) k_rfinal(float* __restrict__ out) {
    int b = blockIdx.x, t = threadIdx.x;
    bool v = t < NCO;
    float s = 0.f;
    if (v) for (int ch = 0; ch < NCHUNK; ch++) s += g_part[(b*NCHUNK+ch)*NCO + t];
    float sn = s*s;
    sn += __shfl_xor_sync(0xffffffffu, sn, 8, 16);
    sn += __shfl_xor_sync(0xffffffffu, sn, 4, 16);
    sn += __shfl_xor_sync(0xffffffffu, sn, 2, 16);
    sn += __shfl_xor_sync(0xffffffffu, sn, 1, 16);
    if (v && (t & 15) == 0) out[b*NCLS + (t >> 4)] = sn / (1.f + sn);
}

extern "C" void kernel_launch(void* const* d_in, const int* in_sizes, int n_in,
                              void* d_out, int out_size) {
    const float* x  = (const float*)d_in[0];
    const float* cw = (const float*)d_in[1];
    const float* cb = (const float*)d_in[2];
    const float* pw = (const float*)d_in[3];
    const float* pb = (const float*)d_in[4];
    const float* rw = (const float*)d_in[5];
    float* out = (float*)d_out;

    k_tw<<<640, 256>>>(cw, pw);
    k_im2col<<<18432, 256>>>(x);
    k_conv1_tc<<<dim3(576, 2), 256>>>(cb);
    k_prim_tc<<<dim3(81, 8), 256>>>();      // 4th launch -> ncu capture target
    k_psquash<<<324, 256>>>(pb);
    k_priors<<<1296, 352>>>(rw);
    k_sum0<<<dim3(12, 64), 344>>>();
    k_s0squash<<<64, 704>>>();
    k_route<<<dim3(NCHUNK, 64), 512>>>();
    k_rsquash<<<64, 704>>>();
    k_route<<<dim3(NCHUNK, 64), 512>>>();
    k_rfinal<<<64, 704>>>(out);
}